// round 9
// baseline (speedup 1.0000x reference)
#include <cuda_runtime.h>
#include <math.h>
#include <stdint.h>

#define Bn 64
#define Tn 512
#define Hn 768
#define Ln 25

__device__ __align__(16) float g_eem  [Bn * Tn * Ln];
__device__ __align__(16) float g_emtag[Bn * Tn];
__device__ float g_llh[Bn];
__device__ int   g_cnt;

typedef unsigned long long ull;

__device__ __forceinline__ ull fma2(ull a, ull b, ull c) {
    ull d; asm("fma.rn.f32x2 %0, %1, %2, %3;" : "=l"(d) : "l"(a), "l"(b), "l"(c)); return d;
}
__device__ __forceinline__ ull mul2(ull a, ull b) {
    ull d; asm("mul.rn.f32x2 %0, %1, %2;" : "=l"(d) : "l"(a), "l"(b)); return d;
}
__device__ __forceinline__ ull add2(ull a, ull b) {
    ull d; asm("add.rn.f32x2 %0, %1, %2;" : "=l"(d) : "l"(a), "l"(b)); return d;
}
__device__ __forceinline__ float lo2(ull a) {
    unsigned l, h; asm("mov.b64 {%0, %1}, %2;" : "=r"(l), "=r"(h) : "l"(a)); return __uint_as_float(l);
}
__device__ __forceinline__ float hi2(ull a) {
    unsigned l, h; asm("mov.b64 {%0, %1}, %2;" : "=r"(l), "=r"(h) : "l"(a)); return __uint_as_float(h);
}
__device__ __forceinline__ ull pack2(float l, float h) {
    ull d; asm("mov.b64 %0, {%1, %2};" : "=l"(d) : "r"(__float_as_uint(l)), "r"(__float_as_uint(h))); return d;
}
__device__ __forceinline__ uint32_t smem_u32(const void* p) {
    uint32_t a; asm("{ .reg .u64 t; cvta.to.shared.u64 t, %1; cvt.u32.u64 %0, t; }" : "=r"(a) : "l"(p));
    return a;
}
__device__ __forceinline__ void cp16(uint32_t dst, const void* src) {
    asm volatile("cp.async.cg.shared.global [%0], [%1], 16;" :: "r"(dst), "l"(src) : "memory");
}
#define CP_COMMIT() asm volatile("cp.async.commit_group;" ::: "memory")

// ---------------------------------------------------------------------------
// Kernel 1: GEMM via mma.sync tf32, 2-stage cp.async pipeline for A,
// register-prefetched direct-from-W staging for B (no wt_prep kernel).
// ---------------------------------------------------------------------------
#define SA0   0
#define SA1   18432
#define SB0   36864
#define SB1   41472
#define SBIAS 46080
#define GSMEM 46208

__global__ __launch_bounds__(128) void gemm_kernel(const float* __restrict__ X,
                                                   const float* __restrict__ W,
                                                   const float* __restrict__ bias,
                                                   const int*   __restrict__ labels) {
    extern __shared__ char smem[];
    const uint32_t sb = smem_u32(smem);
    const int tid  = threadIdx.x;
    const int wid  = tid >> 5;
    const int lid  = tid & 31;
    const int grp  = lid >> 2;
    const int qd   = lid & 3;
    const int row0 = blockIdx.x * 128;

    if (blockIdx.x == 0 && tid == 0) g_cnt = 0;   // graph-replay-safe reset

    float* bias_s = (float*)(smem + SBIAS);
    if (tid < 32) bias_s[tid] = (tid < Ln) ? bias[tid] : 0.f;

    float c_[2][4][4];
#pragma unroll
    for (int mt = 0; mt < 2; ++mt)
#pragma unroll
        for (int nt = 0; nt < 4; ++nt)
#pragma unroll
            for (int r = 0; r < 4; ++r) c_[mt][nt][r] = 0.f;

    // B element ownership: idx = t*128+tid -> n = idx&31, k = idx>>5
    const int bn = tid & 31;
    const int bk0 = tid >> 5;          // k = bk0 + 4*t

#define LDB(CK, BR)                                                             \
    {                                                                           \
        _Pragma("unroll")                                                       \
        for (int t = 0; t < 8; ++t) {                                           \
            int k = bk0 + 4 * t;                                                \
            (BR)[t] = (bn < Ln) ? W[((CK) * 32 + k) * Ln + bn] : 0.f;           \
        }                                                                       \
    }
#define STB(BR, BUF)                                                            \
    {                                                                           \
        float* bs = (float*)(smem + ((BUF) ? SB1 : SB0));                       \
        _Pragma("unroll")                                                       \
        for (int t = 0; t < 8; ++t) bs[bn * 36 + bk0 + 4 * t] = (BR)[t];        \
    }
#define STAGE_A(CK, BUF)                                                        \
    {                                                                           \
        uint32_t ab = sb + ((BUF) ? SA1 : SA0);                                 \
        _Pragma("unroll")                                                       \
        for (int t = 0; t < 8; ++t) {                                           \
            int i = t * 128 + tid;                                              \
            int r = i >> 3, q = i & 7;                                          \
            cp16(ab + (r * 36 + q * 4) * 4,                                     \
                 X + (size_t)(row0 + r) * Hn + (CK) * 32 + q * 4);              \
        }                                                                       \
        CP_COMMIT();                                                            \
    }

    {   // prologue: chunks 0 and 1
        float br0[8], br1[8];
        LDB(0, br0)
        LDB(1, br1)
        STB(br0, 0)
        STB(br1, 1)
        STAGE_A(0, 0)
        STAGE_A(1, 1)
    }

    float brn[8];
    for (int ck = 0; ck < 24; ++ck) {
        const int buf = ck & 1;
        if (ck + 2 < 24) LDB(ck + 2, brn)   // issue LDGs early; stall hidden by mma

        if (ck < 23) asm volatile("cp.async.wait_group 1;" ::: "memory");
        else         asm volatile("cp.async.wait_group 0;" ::: "memory");
        __syncthreads();

        const float* As = (const float*)(smem + (buf ? SA1 : SA0));
        const float* Bs = (const float*)(smem + (buf ? SB1 : SB0));

#pragma unroll
        for (int ks = 0; ks < 4; ++ks) {
            const int k0 = ks * 8;
            uint32_t a[2][4], b[4][2];
#pragma unroll
            for (int mt = 0; mt < 2; ++mt) {
                int r = wid * 32 + mt * 16 + grp;
                a[mt][0] = __float_as_uint(As[r * 36 + k0 + qd]);
                a[mt][1] = __float_as_uint(As[(r + 8) * 36 + k0 + qd]);
                a[mt][2] = __float_as_uint(As[r * 36 + k0 + qd + 4]);
                a[mt][3] = __float_as_uint(As[(r + 8) * 36 + k0 + qd + 4]);
            }
#pragma unroll
            for (int nt = 0; nt < 4; ++nt) {
                int n = nt * 8 + grp;
                b[nt][0] = __float_as_uint(Bs[n * 36 + k0 + qd]);
                b[nt][1] = __float_as_uint(Bs[n * 36 + k0 + qd + 4]);
            }
#pragma unroll
            for (int mt = 0; mt < 2; ++mt)
#pragma unroll
                for (int nt = 0; nt < 4; ++nt)
                    asm volatile(
                        "mma.sync.aligned.m16n8k8.row.col.f32.tf32.tf32.f32 "
                        "{%0,%1,%2,%3}, {%4,%5,%6,%7}, {%8,%9}, {%0,%1,%2,%3};"
                        : "+f"(c_[mt][nt][0]), "+f"(c_[mt][nt][1]),
                          "+f"(c_[mt][nt][2]), "+f"(c_[mt][nt][3])
                        : "r"(a[mt][0]), "r"(a[mt][1]), "r"(a[mt][2]), "r"(a[mt][3]),
                          "r"(b[nt][0]), "r"(b[nt][1]));
        }
        __syncthreads();
        if (ck + 2 < 24) {
            STAGE_A(ck + 2, buf)
            STB(brn, buf)
        }
    }

    // ---- epilogue: pack em + exp(em) to smem; write eem + emtag ----
    float* pem = (float*)(smem + 0);
    float* pee = (float*)(smem + 12800);
#pragma unroll
    for (int mt = 0; mt < 2; ++mt) {
        int rb = wid * 32 + mt * 16 + grp;
#pragma unroll
        for (int nt = 0; nt < 4; ++nt) {
            int col = nt * 8 + 2 * qd;
            if (col < Ln) {
                float v0 = c_[mt][nt][0] + bias_s[col];
                float v2 = c_[mt][nt][2] + bias_s[col];
                pem[rb * Ln + col]       = v0;
                pem[(rb + 8) * Ln + col] = v2;
                pee[rb * Ln + col]       = __expf(v0);
                pee[(rb + 8) * Ln + col] = __expf(v2);
            }
            if (col + 1 < Ln) {
                float v1 = c_[mt][nt][1] + bias_s[col + 1];
                float v3 = c_[mt][nt][3] + bias_s[col + 1];
                pem[rb * Ln + col + 1]       = v1;
                pem[(rb + 8) * Ln + col + 1] = v3;
                pee[rb * Ln + col + 1]       = __expf(v1);
                pee[(rb + 8) * Ln + col + 1] = __expf(v3);
            }
        }
    }
    __syncthreads();
    {
        int lab = labels[row0 + tid];
        g_emtag[row0 + tid] = pem[tid * Ln + lab];
        const float4* s1 = (const float4*)pee;
        float4* g1 = (float4*)(g_eem + (size_t)row0 * Ln);
#pragma unroll
        for (int t = 0; t < 7; ++t) {
            int i = t * 128 + tid;
            if (i < 800) g1[i] = s1[i];
        }
    }
}

// ---------------------------------------------------------------------------
// Kernel 2: CRF + fused final reduce (last-finisher).
// Balanced depth-20 FMA tree; straight SEL (no mask branches).
// ---------------------------------------------------------------------------
#define CRF_STEP(TL, TG)                                                        \
    {                                                                           \
        asm volatile("st.shared.b32 [%0], %1;"                                  \
                     :: "r"(pbase + 4u * (unsigned)j),                          \
                        "r"(__float_as_uint(p)) : "memory");                    \
        ull w0,w1,w2,w3,w4,w5,w6,w7,w8,w9,w10,w11,w12;                          \
        asm volatile("ld.shared.v2.u64 {%0,%1}, [%2];"                          \
                     : "=l"(w0), "=l"(w1) : "r"(pbase));                        \
        asm volatile("ld.shared.v2.u64 {%0,%1}, [%2];"                          \
                     : "=l"(w2), "=l"(w3) : "r"(pbase + 16));                   \
        asm volatile("ld.shared.v2.u64 {%0,%1}, [%2];"                          \
                     : "=l"(w4), "=l"(w5) : "r"(pbase + 32));                   \
        asm volatile("ld.shared.v2.u64 {%0,%1}, [%2];"                          \
                     : "=l"(w6), "=l"(w7) : "r"(pbase + 48));                   \
        asm volatile("ld.shared.v2.u64 {%0,%1}, [%2];"                          \
                     : "=l"(w8), "=l"(w9) : "r"(pbase + 64));                   \
        asm volatile("ld.shared.v2.u64 {%0,%1}, [%2];"                          \
                     : "=l"(w10), "=l"(w11) : "r"(pbase + 80));                 \
        asm volatile("ld.shared.u64 %0, [%1];"                                  \
                     : "=l"(w12) : "r"(pbase + 96));                            \
        ull A0 = mul2(w0, et2[0]);                                              \
        ull A1 = mul2(w1, et2[1]);                                              \
        ull A2 = mul2(w2, et2[2]);                                              \
        ull A3 = mul2(w3, et2[3]);                                              \
        ull A4 = mul2(w4, et2[4]);                                              \
        ull A5 = mul2(w5, et2[5]);                                              \
        ull A6 = mul2(w6, et2[6]);                                              \
        A0 = fma2(w7,  et2[7],  A0);                                            \
        A1 = fma2(w8,  et2[8],  A1);                                            \
        A2 = fma2(w9,  et2[9],  A2);                                            \
        A3 = fma2(w10, et2[10], A3);                                            \
        A4 = fma2(w11, et2[11], A4);                                            \
        A5 = fma2(w12, et2[12], A5);                                            \
        ull T0 = add2(A0, A1);                                                  \
        ull T1 = add2(A2, A3);                                                  \
        ull T2 = add2(A4, A5);                                                  \
        T0 = add2(T0, T1);                                                      \
        T2 = add2(T2, A6);                                                      \
        T0 = add2(T0, T2);                                                      \
        float pn = (lo2(T0) + hi2(T0)) * emsb[(TL) * Ln + jc];                  \
        p = smask[TG] ? pn : p;                                                 \
    }

#define CRF_RENORM                                                              \
    {                                                                           \
        unsigned mx = __reduce_max_sync(0xffffffffu, __float_as_uint(p));       \
        int e = (int)(mx >> 23);                                                \
        float sc = __uint_as_float((unsigned)(253 - e) << 23);                  \
        p *= sc;                                                                \
        C += (float)(e - 126) * 0.6931471805599453f;                            \
    }

#define STAGE_EMS(C, BUF)                                                       \
    {                                                                           \
        const float* srcp = eemb + (C) * 1600;                                  \
        uint32_t dstb = (BUF) ? emsb1 : emsb0;                                  \
        for (int i = j; i < 400; i += 32)                                       \
            cp16(dstb + 16u * (unsigned)i, srcp + 4 * i);                       \
        CP_COMMIT();                                                            \
    }

__global__ __launch_bounds__(32) void crf_kernel(const int* __restrict__ mask,
                                                 const int* __restrict__ labels,
                                                 const float* __restrict__ trans,
                                                 const float* __restrict__ start_t,
                                                 const float* __restrict__ end_t,
                                                 float* __restrict__ out) {
    const int b  = blockIdx.x;
    const int j  = threadIdx.x;
    const int jc = (j < Ln) ? j : (Ln - 1);
    const bool lane_ok = (j < Ln);

    const float* eemb   = g_eem + (size_t)b * Tn * Ln;
    const float* emtagb = g_emtag + b * Tn;
    const int*   lb     = labels + b * Tn;

    __shared__ __align__(16) float ems2[2][1600];
    __shared__ __align__(16) float pbuf[32];
    __shared__ int smask[Tn];
    const uint32_t pbase = smem_u32(pbuf);
    const uint32_t emsb0 = smem_u32(ems2[0]);
    const uint32_t emsb1 = smem_u32(ems2[1]);

    STAGE_EMS(0, 0)
    STAGE_EMS(1, 1)

    for (int t = j; t < Tn; t += 32) smask[t] = mask[b * Tn + t];

    // ---- numerator (overlaps with cp.async fill) ----
    float numv = 0.f; int msum = 0;
    for (int t = j; t < Tn; t += 32) {
        int m = smask[t];
        msum += m;
        if (t == 0)  numv += start_t[lb[0]] + emtagb[0];
        else if (m)  numv += trans[lb[t - 1] * Ln + lb[t]] + emtagb[t];
    }
#pragma unroll
    for (int off = 16; off; off >>= 1) {
        numv += __shfl_xor_sync(0xffffffffu, numv, off);
        msum += __shfl_xor_sync(0xffffffffu, msum, off);
    }

    ull et2[13];
#pragma unroll
    for (int i = 0; i < 13; ++i) {
        float lo = __expf(trans[(2 * i) * Ln + jc]);
        float hi = (2 * i + 1 < Ln) ? __expf(trans[(2 * i + 1) * Ln + jc]) : 0.f;
        et2[i] = pack2(lo, hi);
    }
    const float eend = __expf(end_t[jc]);

    float p = 0.f, C = 0.f;

    for (int c = 0; c < 8; ++c) {
        if (c < 7) asm volatile("cp.async.wait_group 1;" ::: "memory");
        else       asm volatile("cp.async.wait_group 0;" ::: "memory");
        __syncwarp();
        const float* emsb = ems2[c & 1];
        const int tbase = c * 64;

        if (c == 0) {
            p = __expf(start_t[jc]) * emsb[jc];
#pragma unroll
            for (int u = 1; u < 16; ++u) CRF_STEP(u, u)
            CRF_RENORM
#pragma unroll
            for (int g = 1; g < 4; ++g) {
#pragma unroll
                for (int u = 0; u < 16; ++u) CRF_STEP(g * 16 + u, g * 16 + u)
                CRF_RENORM
            }
        } else {
#pragma unroll
            for (int g = 0; g < 4; ++g) {
#pragma unroll
                for (int u = 0; u < 16; ++u) CRF_STEP(g * 16 + u, tbase + g * 16 + u)
                CRF_RENORM
            }
        }
        if (c + 2 < 8) STAGE_EMS(c + 2, c & 1)
    }

    float tot = lane_ok ? p * eend : 0.f;
#pragma unroll
    for (int off = 16; off; off >>= 1) tot += __shfl_xor_sync(0xffffffffu, tot, off);
    float denom = C + __logf(tot);

    if (j == 0) {
        int last = msum - 1;
        g_llh[b] = (numv + end_t[lb[last]]) - denom;
        __threadfence();
        int old = atomicAdd(&g_cnt, 1);
        if (old == Bn - 1) {
            __threadfence();
            float s = 0.f;
#pragma unroll 8
            for (int i = 0; i < Bn; ++i) s += __ldcv(&g_llh[i]);
            out[0] = -s * (1.0f / 64.0f);
        }
    }
}

// ---------------------------------------------------------------------------
extern "C" void kernel_launch(void* const* d_in, const int* in_sizes, int n_in,
                              void* d_out, int out_size) {
    const float* X      = (const float*)d_in[0];
    const int*   mask   = (const int*)  d_in[1];
    const int*   labels = (const int*)  d_in[2];
    const float* W      = (const float*)d_in[3];
    const float* bias   = (const float*)d_in[4];
    const float* trans  = (const float*)d_in[5];
    const float* st     = (const float*)d_in[6];
    const float* en     = (const float*)d_in[7];
    float* out = (float*)d_out;

    gemm_kernel<<<256, 128, GSMEM>>>(X, W, bias, labels);
    crf_kernel<<<Bn, 32>>>(mask, labels, trans, st, en, out);
}

// round 10
// speedup vs baseline: 1.0603x; 1.0603x over previous
#include <cuda_runtime.h>
#include <math.h>
#include <stdint.h>

#define Bn 64
#define Tn 512
#define Hn 768
#define Ln 25

__device__ __align__(16) float g_eem  [Bn * Tn * Ln];
__device__ __align__(16) float g_emtag[Bn * Tn];
__device__ float g_llh[Bn];
__device__ int   g_cnt;

typedef unsigned long long ull;

__device__ __forceinline__ ull fma2(ull a, ull b, ull c) {
    ull d; asm("fma.rn.f32x2 %0, %1, %2, %3;" : "=l"(d) : "l"(a), "l"(b), "l"(c)); return d;
}
__device__ __forceinline__ ull mul2(ull a, ull b) {
    ull d; asm("mul.rn.f32x2 %0, %1, %2;" : "=l"(d) : "l"(a), "l"(b)); return d;
}
__device__ __forceinline__ ull add2(ull a, ull b) {
    ull d; asm("add.rn.f32x2 %0, %1, %2;" : "=l"(d) : "l"(a), "l"(b)); return d;
}
__device__ __forceinline__ float lo2(ull a) {
    unsigned l, h; asm("mov.b64 {%0, %1}, %2;" : "=r"(l), "=r"(h) : "l"(a)); return __uint_as_float(l);
}
__device__ __forceinline__ float hi2(ull a) {
    unsigned l, h; asm("mov.b64 {%0, %1}, %2;" : "=r"(l), "=r"(h) : "l"(a)); return __uint_as_float(h);
}
__device__ __forceinline__ ull pack2(float l, float h) {
    ull d; asm("mov.b64 %0, {%1, %2};" : "=l"(d) : "r"(__float_as_uint(l)), "r"(__float_as_uint(h))); return d;
}
__device__ __forceinline__ uint32_t smem_u32(const void* p) {
    uint32_t a; asm("{ .reg .u64 t; cvta.to.shared.u64 t, %1; cvt.u32.u64 %0, t; }" : "=r"(a) : "l"(p));
    return a;
}
__device__ __forceinline__ void cp16(uint32_t dst, const void* src) {
    asm volatile("cp.async.cg.shared.global [%0], [%1], 16;" :: "r"(dst), "l"(src) : "memory");
}
__device__ __forceinline__ void cp4(uint32_t dst, const void* src) {
    asm volatile("cp.async.ca.shared.global [%0], [%1], 4;" :: "r"(dst), "l"(src) : "memory");
}
#define CP_COMMIT() asm volatile("cp.async.commit_group;" ::: "memory")

// ---------------------------------------------------------------------------
// Kernel 1: GEMM via mma.sync tf32. A: 16B cp.async SW-free layout (pad 36).
// B: raw W chunk (32 rows x 25) bounced via 4B cp.async into Wraw[32][40]
// (pad 40 -> conflict-free B-fragment LDS). 2-stage pipeline. No prep kernel.
// ---------------------------------------------------------------------------
#define SA0   0
#define SA1   18432
#define SW0   36864
#define SW1   41984
#define SBIAS 47104
#define GSMEM 47232

__global__ __launch_bounds__(128) void gemm_kernel(const float* __restrict__ X,
                                                   const float* __restrict__ W,
                                                   const float* __restrict__ bias,
                                                   const int*   __restrict__ labels) {
    extern __shared__ char smem[];
    const uint32_t sb = smem_u32(smem);
    const int tid  = threadIdx.x;
    const int wid  = tid >> 5;
    const int lid  = tid & 31;
    const int grp  = lid >> 2;
    const int qd   = lid & 3;
    const int row0 = blockIdx.x * 128;

    if (blockIdx.x == 0 && tid == 0) g_cnt = 0;   // graph-replay-safe reset

    float* bias_s = (float*)(smem + SBIAS);
    if (tid < 32) bias_s[tid] = (tid < Ln) ? bias[tid] : 0.f;

    float c_[2][4][4];
#pragma unroll
    for (int mt = 0; mt < 2; ++mt)
#pragma unroll
        for (int nt = 0; nt < 4; ++nt)
#pragma unroll
            for (int r = 0; r < 4; ++r) c_[mt][nt][r] = 0.f;

#define STAGE(CK, BUF)                                                          \
    {                                                                           \
        uint32_t ab = sb + ((BUF) ? SA1 : SA0);                                 \
        uint32_t wb = sb + ((BUF) ? SW1 : SW0);                                 \
        _Pragma("unroll")                                                       \
        for (int t = 0; t < 8; ++t) {                                           \
            int i = t * 128 + tid;                                              \
            int r = i >> 3, q = i & 7;                                          \
            cp16(ab + (r * 36 + q * 4) * 4,                                     \
                 X + (size_t)(row0 + r) * Hn + (CK) * 32 + q * 4);              \
        }                                                                       \
        _Pragma("unroll")                                                       \
        for (int t = 0; t < 7; ++t) {                                           \
            int i = t * 128 + tid;                                              \
            if (i < 800) {                                                      \
                int k = i / 25, n = i - k * 25;                                 \
                cp4(wb + (k * 40 + n) * 4, W + (CK) * 800 + i);                 \
            }                                                                   \
        }                                                                       \
        CP_COMMIT();                                                            \
    }

    STAGE(0, 0)
    STAGE(1, 1)

    for (int ck = 0; ck < 24; ++ck) {
        if (ck < 23) asm volatile("cp.async.wait_group 1;" ::: "memory");
        else         asm volatile("cp.async.wait_group 0;" ::: "memory");
        __syncthreads();

        const int buf = ck & 1;
        const float* As = (const float*)(smem + (buf ? SA1 : SA0));
        const float* Ws = (const float*)(smem + (buf ? SW1 : SW0));

#pragma unroll
        for (int ks = 0; ks < 4; ++ks) {
            const int k0 = ks * 8;
            uint32_t a[2][4], b[4][2];
#pragma unroll
            for (int mt = 0; mt < 2; ++mt) {
                int r = wid * 32 + mt * 16 + grp;
                a[mt][0] = __float_as_uint(As[r * 36 + k0 + qd]);
                a[mt][1] = __float_as_uint(As[(r + 8) * 36 + k0 + qd]);
                a[mt][2] = __float_as_uint(As[r * 36 + k0 + qd + 4]);
                a[mt][3] = __float_as_uint(As[(r + 8) * 36 + k0 + qd + 4]);
            }
#pragma unroll
            for (int nt = 0; nt < 4; ++nt) {
                int n = nt * 8 + grp;
                float b0 = (n < Ln) ? Ws[(k0 + qd) * 40 + n] : 0.f;
                float b1 = (n < Ln) ? Ws[(k0 + qd + 4) * 40 + n] : 0.f;
                b[nt][0] = __float_as_uint(b0);
                b[nt][1] = __float_as_uint(b1);
            }
#pragma unroll
            for (int mt = 0; mt < 2; ++mt)
#pragma unroll
                for (int nt = 0; nt < 4; ++nt)
                    asm volatile(
                        "mma.sync.aligned.m16n8k8.row.col.f32.tf32.tf32.f32 "
                        "{%0,%1,%2,%3}, {%4,%5,%6,%7}, {%8,%9}, {%0,%1,%2,%3};"
                        : "+f"(c_[mt][nt][0]), "+f"(c_[mt][nt][1]),
                          "+f"(c_[mt][nt][2]), "+f"(c_[mt][nt][3])
                        : "r"(a[mt][0]), "r"(a[mt][1]), "r"(a[mt][2]), "r"(a[mt][3]),
                          "r"(b[nt][0]), "r"(b[nt][1]));
        }
        __syncthreads();
        if (ck + 2 < 24) STAGE(ck + 2, buf)
    }

    // ---- epilogue: pack em + exp(em) to smem; write eem + emtag ----
    float* pem = (float*)(smem + 0);
    float* pee = (float*)(smem + 12800);
#pragma unroll
    for (int mt = 0; mt < 2; ++mt) {
        int rb = wid * 32 + mt * 16 + grp;
#pragma unroll
        for (int nt = 0; nt < 4; ++nt) {
            int col = nt * 8 + 2 * qd;
            if (col < Ln) {
                float v0 = c_[mt][nt][0] + bias_s[col];
                float v2 = c_[mt][nt][2] + bias_s[col];
                pem[rb * Ln + col]       = v0;
                pem[(rb + 8) * Ln + col] = v2;
                pee[rb * Ln + col]       = __expf(v0);
                pee[(rb + 8) * Ln + col] = __expf(v2);
            }
            if (col + 1 < Ln) {
                float v1 = c_[mt][nt][1] + bias_s[col + 1];
                float v3 = c_[mt][nt][3] + bias_s[col + 1];
                pem[rb * Ln + col + 1]       = v1;
                pem[(rb + 8) * Ln + col + 1] = v3;
                pee[rb * Ln + col + 1]       = __expf(v1);
                pee[(rb + 8) * Ln + col + 1] = __expf(v3);
            }
        }
    }
    __syncthreads();
    {
        int lab = labels[row0 + tid];
        g_emtag[row0 + tid] = pem[tid * Ln + lab];
        const float4* s1 = (const float4*)pee;
        float4* g1 = (float4*)(g_eem + (size_t)row0 * Ln);
#pragma unroll
        for (int t = 0; t < 7; ++t) {
            int i = t * 128 + tid;
            if (i < 800) g1[i] = s1[i];
        }
    }
}

// ---------------------------------------------------------------------------
// Kernel 2: CRF + fused last-finisher reduce.
// Chain diet: mask in register bitmask (ALU select, off-chain); emission
// prefetched one step ahead (LDS issued before the step's STS, covered).
// ---------------------------------------------------------------------------
#define CRF_STEP(TL, TG)                                                        \
    {                                                                           \
        float emn = ((TL) + 1 < 64) ? emsb[((TL) + 1) * Ln + jc] : 0.f;         \
        asm volatile("st.shared.b32 [%0], %1;"                                  \
                     :: "r"(pbase + 4u * (unsigned)j),                          \
                        "r"(__float_as_uint(p)) : "memory");                    \
        ull w0,w1,w2,w3,w4,w5,w6,w7,w8,w9,w10,w11,w12;                          \
        asm volatile("ld.shared.v2.u64 {%0,%1}, [%2];"                          \
                     : "=l"(w0), "=l"(w1) : "r"(pbase));                        \
        asm volatile("ld.shared.v2.u64 {%0,%1}, [%2];"                          \
                     : "=l"(w2), "=l"(w3) : "r"(pbase + 16));                   \
        asm volatile("ld.shared.v2.u64 {%0,%1}, [%2];"                          \
                     : "=l"(w4), "=l"(w5) : "r"(pbase + 32));                   \
        asm volatile("ld.shared.v2.u64 {%0,%1}, [%2];"                          \
                     : "=l"(w6), "=l"(w7) : "r"(pbase + 48));                   \
        asm volatile("ld.shared.v2.u64 {%0,%1}, [%2];"                          \
                     : "=l"(w8), "=l"(w9) : "r"(pbase + 64));                   \
        asm volatile("ld.shared.v2.u64 {%0,%1}, [%2];"                          \
                     : "=l"(w10), "=l"(w11) : "r"(pbase + 80));                 \
        asm volatile("ld.shared.u64 %0, [%1];"                                  \
                     : "=l"(w12) : "r"(pbase + 96));                            \
        ull A0 = mul2(w0, et2[0]);                                              \
        ull A1 = mul2(w1, et2[1]);                                              \
        ull A2 = mul2(w2, et2[2]);                                              \
        ull A3 = mul2(w3, et2[3]);                                              \
        ull A4 = mul2(w4, et2[4]);                                              \
        ull A5 = mul2(w5, et2[5]);                                              \
        ull A6 = mul2(w6, et2[6]);                                              \
        A0 = fma2(w7,  et2[7],  A0);                                            \
        A1 = fma2(w8,  et2[8],  A1);                                            \
        A2 = fma2(w9,  et2[9],  A2);                                            \
        A3 = fma2(w10, et2[10], A3);                                            \
        A4 = fma2(w11, et2[11], A4);                                            \
        A5 = fma2(w12, et2[12], A5);                                            \
        ull T0 = add2(A0, A1);                                                  \
        ull T1 = add2(A2, A3);                                                  \
        ull T2 = add2(A4, A5);                                                  \
        T0 = add2(T0, T1);                                                      \
        T2 = add2(T2, A6);                                                      \
        T0 = add2(T0, T2);                                                      \
        float pn = (lo2(T0) + hi2(T0)) * emc;                                   \
        unsigned mb = (mwords[(TG) >> 5] >> ((TG) & 31)) & 1u;                  \
        p = mb ? pn : p;                                                        \
        emc = emn;                                                              \
    }

#define CRF_RENORM                                                              \
    {                                                                           \
        unsigned mx = __reduce_max_sync(0xffffffffu, __float_as_uint(p));       \
        int e = (int)(mx >> 23);                                                \
        float sc = __uint_as_float((unsigned)(253 - e) << 23);                  \
        p *= sc;                                                                \
        C += (float)(e - 126) * 0.6931471805599453f;                            \
    }

#define STAGE_EMS(C, BUF)                                                       \
    {                                                                           \
        const float* srcp = eemb + (C) * 1600;                                  \
        uint32_t dstb = (BUF) ? emsb1 : emsb0;                                  \
        for (int i = j; i < 400; i += 32)                                       \
            cp16(dstb + 16u * (unsigned)i, srcp + 4 * i);                       \
        CP_COMMIT();                                                            \
    }

__global__ __launch_bounds__(32) void crf_kernel(const int* __restrict__ mask,
                                                 const int* __restrict__ labels,
                                                 const float* __restrict__ trans,
                                                 const float* __restrict__ start_t,
                                                 const float* __restrict__ end_t,
                                                 float* __restrict__ out) {
    const int b  = blockIdx.x;
    const int j  = threadIdx.x;
    const int jc = (j < Ln) ? j : (Ln - 1);
    const bool lane_ok = (j < Ln);

    const float* eemb   = g_eem + (size_t)b * Tn * Ln;
    const float* emtagb = g_emtag + b * Tn;
    const int*   lb     = labels + b * Tn;

    __shared__ __align__(16) float ems2[2][1600];
    __shared__ __align__(16) float pbuf[32];
    __shared__ int smask[Tn];
    const uint32_t pbase = smem_u32(pbuf);
    const uint32_t emsb0 = smem_u32(ems2[0]);
    const uint32_t emsb1 = smem_u32(ems2[1]);

    STAGE_EMS(0, 0)
    STAGE_EMS(1, 1)

    for (int t = j; t < Tn; t += 32) smask[t] = mask[b * Tn + t];

    // mask -> 16-word register bitmask (bit t of mwords[t>>5])
    unsigned mwords[16];
#pragma unroll
    for (int w = 0; w < 16; ++w)
        mwords[w] = __ballot_sync(0xffffffffu, smask[w * 32 + j]);

    // ---- numerator (overlaps with cp.async fill) ----
    float numv = 0.f; int msum = 0;
    for (int t = j; t < Tn; t += 32) {
        int m = smask[t];
        msum += m;
        if (t == 0)  numv += start_t[lb[0]] + emtagb[0];
        else if (m)  numv += trans[lb[t - 1] * Ln + lb[t]] + emtagb[t];
    }
#pragma unroll
    for (int off = 16; off; off >>= 1) {
        numv += __shfl_xor_sync(0xffffffffu, numv, off);
        msum += __shfl_xor_sync(0xffffffffu, msum, off);
    }

    ull et2[13];
#pragma unroll
    for (int i = 0; i < 13; ++i) {
        float lo = __expf(trans[(2 * i) * Ln + jc]);
        float hi = (2 * i + 1 < Ln) ? __expf(trans[(2 * i + 1) * Ln + jc]) : 0.f;
        et2[i] = pack2(lo, hi);
    }
    const float eend = __expf(end_t[jc]);

    float p = 0.f, C = 0.f;

    for (int c = 0; c < 8; ++c) {
        if (c < 7) asm volatile("cp.async.wait_group 1;" ::: "memory");
        else       asm volatile("cp.async.wait_group 0;" ::: "memory");
        __syncwarp();
        const float* emsb = ems2[c & 1];
        const int tbase = c * 64;

        if (c == 0) {
            p = __expf(start_t[jc]) * emsb[jc];
            float emc = emsb[Ln + jc];
#pragma unroll
            for (int u = 1; u < 16; ++u) CRF_STEP(u, u)
            CRF_RENORM
#pragma unroll
            for (int g = 1; g < 4; ++g) {
#pragma unroll
                for (int u = 0; u < 16; ++u) CRF_STEP(g * 16 + u, g * 16 + u)
                CRF_RENORM
            }
        } else {
            float emc = emsb[jc];
#pragma unroll
            for (int g = 0; g < 4; ++g) {
#pragma unroll
                for (int u = 0; u < 16; ++u) CRF_STEP(g * 16 + u, tbase + g * 16 + u)
                CRF_RENORM
            }
        }
        if (c + 2 < 8) STAGE_EMS(c + 2, c & 1)
    }

    float tot = lane_ok ? p * eend : 0.f;
#pragma unroll
    for (int off = 16; off; off >>= 1) tot += __shfl_xor_sync(0xffffffffu, tot, off);
    float denom = C + __logf(tot);

    if (j == 0) {
        int last = msum - 1;
        g_llh[b] = (numv + end_t[lb[last]]) - denom;
        __threadfence();
        int old = atomicAdd(&g_cnt, 1);
        if (old == Bn - 1) {
            __threadfence();
            float s = 0.f;
#pragma unroll 8
            for (int i = 0; i < Bn; ++i) s += __ldcv(&g_llh[i]);
            out[0] = -s * (1.0f / 64.0f);
        }
    }
}

// ---------------------------------------------------------------------------
extern "C" void kernel_launch(void* const* d_in, const int* in_sizes, int n_in,
                              void* d_out, int out_size) {
    const float* X      = (const float*)d_in[0];
    const int*   mask   = (const int*)  d_in[1];
    const int*   labels = (const int*)  d_in[2];
    const float* W      = (const float*)d_in[3];
    const float* bias   = (const float*)d_in[4];
    const float* trans  = (const float*)d_in[5];
    const float* st     = (const float*)d_in[6];
    const float* en     = (const float*)d_in[7];
    float* out = (float*)d_out;

    gemm_kernel<<<256, 128, GSMEM>>>(X, W, bias, labels);
    crf_kernel<<<Bn, 32>>>(mask, labels, trans, st, en, out);
}